// round 7
// baseline (speedup 1.0000x reference)
#include <cuda_runtime.h>
#include <cstdint>

// GungnirHalfKA fused NNUE eval for GB300.
// Inputs (metadata order):
//  0 w_feats  int32 [B*32]      1 w_offsets int32 [B]
//  2 b_feats  int32 [B*32]      3 b_offsets int32 [B]
//  4 stm      int32 [B]         5 bucket    int32 [B]
//  6 ft_weight f32 [45056,1024] 7 ft_bias   f32 [1024]
//  8 psqt_weight f32 [45056,8]
//  9 fc0_w f32 [8,16,1024]     10 fc0_b f32 [8,16]
// 11 fc1_w f32 [8,32,32]       12 fc1_b f32 [8,32]
// 13 fc2_w f32 [8,1,32]        14 fc2_b f32 [8,1]
// Output: f32 [B]
//
// fake_quant(ft_weight,16) values fit int8 (verified in round 3). Table is
// stored BIASED uint8 (q+128); sparse sums run as carry-free packed uint16x2
// adds. Phase 1 uses LDG.128 via __ldcg (L2-only, no L1 allocate): 256
// threads = 2 halves x 2 feat-groups x 64 threads x 16 columns; partials
// combined through shared memory.

#define FT_IN  45056
#define FT_OUT 1024
#define NBUCK  8

__device__ unsigned char g_ftw_q[(size_t)FT_IN * FT_OUT];   // biased uint8, 46 MB
__device__ signed char   g_fc0_q[NBUCK * 16 * FT_OUT];      // signed int8, 128 KB

__device__ __forceinline__ unsigned int qbias8(float v) {
    return (unsigned int)fminf(fmaxf(rintf(v) + 128.f, 0.f), 255.f);
}

// Prelude: quantize ft_weight (biased uint8, 16 floats/thread) + fc0_w (int8).
__global__ void __launch_bounds__(256) k_quant(
    const float* __restrict__ ftw, const float* __restrict__ fc0w,
    int n16, int nfc4)
{
    const int i = blockIdx.x * blockDim.x + threadIdx.x;
    if (i < n16) {
        const float4* src = reinterpret_cast<const float4*>(ftw) + i * 4;
        float4 v0 = src[0], v1 = src[1], v2 = src[2], v3 = src[3];
        uint4 q;
        q.x = qbias8(v0.x) | (qbias8(v0.y) << 8) | (qbias8(v0.z) << 16) | (qbias8(v0.w) << 24);
        q.y = qbias8(v1.x) | (qbias8(v1.y) << 8) | (qbias8(v1.z) << 16) | (qbias8(v1.w) << 24);
        q.z = qbias8(v2.x) | (qbias8(v2.y) << 8) | (qbias8(v2.z) << 16) | (qbias8(v2.w) << 24);
        q.w = qbias8(v3.x) | (qbias8(v3.y) << 8) | (qbias8(v3.z) << 16) | (qbias8(v3.w) << 24);
        reinterpret_cast<uint4*>(g_ftw_q)[i] = q;
    }
    if (i < nfc4) {
        float4 v = reinterpret_cast<const float4*>(fc0w)[i];
        char4 q;
        q.x = (signed char)fminf(fmaxf(rintf(v.x), -128.f), 127.f);
        q.y = (signed char)fminf(fmaxf(rintf(v.y), -128.f), 127.f);
        q.z = (signed char)fminf(fmaxf(rintf(v.z), -128.f), 127.f);
        q.w = (signed char)fminf(fmaxf(rintf(v.w), -128.f), 127.f);
        reinterpret_cast<char4*>(g_fc0_q)[i] = q;
    }
}

__device__ __forceinline__ float clip127(float x) {
    return fminf(fmaxf(x, 0.f), 127.f);
}
__device__ __forceinline__ float q8(float x) {
    return fminf(fmaxf(rintf(x), -128.f), 127.f);
}

__global__ void __launch_bounds__(256) k_main(
    const int* __restrict__ wfeat, const int* __restrict__ woff,
    const int* __restrict__ bfeat, const int* __restrict__ boff,
    const int* __restrict__ stm,   const int* __restrict__ bucket,
    const float* __restrict__ ft_bias, const float* __restrict__ psqt,
    const float* __restrict__ fc0_b,
    const float* __restrict__ fc1_w, const float* __restrict__ fc1_b,
    const float* __restrict__ fc2_w, const float* __restrict__ fc2_b,
    float* __restrict__ out, int B, int n_wf, int n_bf)
{
    __shared__ float        s_acc[2][FT_OUT];      // 8 KB
    __shared__ float        s_ft[FT_OUT];          // 4 KB
    __shared__ unsigned int s_p[4][64][8];         // 8 KB packed partials
    __shared__ float        s_o0[16];

    const int b    = blockIdx.x;
    const int tid  = threadIdx.x;
    const int half = tid >> 7;           // 0: white, 1: black
    const int grp  = (tid >> 6) & 1;     // feature subgroup
    const int l16  = tid & 63;           // owns cols [16*l16, 16*l16+16)

    // ---- Phase 1: sparse gather, LDG.128 L2-only, packed uint16x2 accum ----
    const int* feats = half ? bfeat : wfeat;
    const int* offs  = half ? boff  : woff;
    const int  nf    = half ? n_bf  : n_wf;
    const int  start = offs[b];
    const int  end   = (b + 1 < B) ? offs[b + 1] : nf;

    {
        const unsigned char* base = g_ftw_q + (unsigned)l16 * 16u;
        unsigned int q0 = 0, q1 = 0, q2 = 0, q3 = 0, q4 = 0, q5 = 0, q6 = 0, q7 = 0;
        #pragma unroll 4
        for (int k = start + grp; k < end; k += 2) {
            const unsigned int f = (unsigned int)feats[k];
            uint4 v = __ldcg(reinterpret_cast<const uint4*>(base + ((size_t)f << 10)));
            q0 += __byte_perm(v.x, 0u, 0x4140);
            q1 += __byte_perm(v.x, 0u, 0x4342);
            q2 += __byte_perm(v.y, 0u, 0x4140);
            q3 += __byte_perm(v.y, 0u, 0x4342);
            q4 += __byte_perm(v.z, 0u, 0x4140);
            q5 += __byte_perm(v.z, 0u, 0x4342);
            q6 += __byte_perm(v.w, 0u, 0x4140);
            q7 += __byte_perm(v.w, 0u, 0x4342);
        }
        unsigned int* sp = s_p[half * 2 + grp][l16];
        sp[0] = q0; sp[1] = q1; sp[2] = q2; sp[3] = q3;
        sp[4] = q4; sp[5] = q5; sp[6] = q6; sp[7] = q7;
    }
    __syncthreads();

    // ---- Phase 1b: combine groups, unbias, add quantized ft_bias ----
    {
        const int h = tid & 127;                 // owns cols [8h, 8h+8)
        const unsigned int* pa = &s_p[half * 2 + 0][h >> 1][(h & 1) * 4];
        const unsigned int* pb = &s_p[half * 2 + 1][h >> 1][(h & 1) * 4];
        const unsigned int p0 = pa[0] + pb[0];
        const unsigned int p1 = pa[1] + pb[1];
        const unsigned int p2 = pa[2] + pb[2];
        const unsigned int p3 = pa[3] + pb[3];
        const float bias = 128.f * (float)(end - start);
        float4 b0 = reinterpret_cast<const float4*>(ft_bias)[h * 2];
        float4 b1 = reinterpret_cast<const float4*>(ft_bias)[h * 2 + 1];
        float* dst = s_acc[half] + h * 8;
        dst[0] = (float)(p0 & 0xFFFFu) - bias + fminf(fmaxf(rintf(b0.x), -32768.f), 32767.f);
        dst[1] = (float)(p0 >> 16)     - bias + fminf(fmaxf(rintf(b0.y), -32768.f), 32767.f);
        dst[2] = (float)(p1 & 0xFFFFu) - bias + fminf(fmaxf(rintf(b0.z), -32768.f), 32767.f);
        dst[3] = (float)(p1 >> 16)     - bias + fminf(fmaxf(rintf(b0.w), -32768.f), 32767.f);
        dst[4] = (float)(p2 & 0xFFFFu) - bias + fminf(fmaxf(rintf(b1.x), -32768.f), 32767.f);
        dst[5] = (float)(p2 >> 16)     - bias + fminf(fmaxf(rintf(b1.y), -32768.f), 32767.f);
        dst[6] = (float)(p3 & 0xFFFFu) - bias + fminf(fmaxf(rintf(b1.z), -32768.f), 32767.f);
        dst[7] = (float)(p3 >> 16)     - bias + fminf(fmaxf(rintf(b1.w), -32768.f), 32767.f);
    }
    __syncthreads();

    // ---- Phase 2: stm select + pairwise clipped product ----
    const int st = stm[b];
    const float* as = s_acc[st];
    const float* ao = s_acc[st ^ 1];
    for (int j = tid; j < 512; j += 256) {
        float lo = clip127(as[j]);
        float hi = clip127(as[j + 512]);
        s_ft[j] = lo * hi * (1.f / 128.f);
        lo = clip127(ao[j]);
        hi = clip127(ao[j + 512]);
        s_ft[j + 512] = lo * hi * (1.f / 128.f);
    }
    __syncthreads();

    // ---- Phase 3: fc0 (16 x 1024), int8 weights, 8 warps x 2 outputs ----
    const int s    = bucket[b];
    const int warp = tid >> 5;
    const int lane = tid & 31;
    {
        const char4*  w8  = reinterpret_cast<const char4*>(g_fc0_q + s * 16 * FT_OUT);
        const float4* ft4 = reinterpret_cast<const float4*>(s_ft);
        const int oA = warp * 2, oB = warp * 2 + 1;
        float oa = 0.f, ob = 0.f;
        #pragma unroll
        for (int k = 0; k < 8; ++k) {
            const int idx = lane + 32 * k;
            float4 f = ft4[idx];
            char4 wa = w8[oA * 256 + idx];
            char4 wb = w8[oB * 256 + idx];
            oa += f.x * wa.x + f.y * wa.y + f.z * wa.z + f.w * wa.w;
            ob += f.x * wb.x + f.y * wb.y + f.z * wb.z + f.w * wb.w;
        }
        #pragma unroll
        for (int o = 16; o; o >>= 1) {
            oa += __shfl_down_sync(0xffffffffu, oa, o);
            ob += __shfl_down_sync(0xffffffffu, ob, o);
        }
        if (lane == 0) {
            s_o0[oA] = oa + rintf(fc0_b[s * 16 + oA]);
            s_o0[oB] = ob + rintf(fc0_b[s * 16 + oB]);
        }
    }
    __syncthreads();

    // ---- Phase 4: slab -> fc1 -> fc2 -> skip + psqt (warp 0 only) ----
    if (warp == 0) {
        float slab = 0.f;
        if (lane < 15) {
            float v = s_o0[lane];
            slab = fminf(v * v * (1.f / 524288.f), 127.f);
        } else if (lane < 30) {
            slab = clip127(s_o0[lane - 15] * (1.f / 64.f));
        }

        const float* w1 = fc1_w + (s * 32 + lane) * 32;
        float o1 = 0.f;
        #pragma unroll
        for (int i = 0; i < 32; ++i) {
            float si = __shfl_sync(0xffffffffu, slab, i);
            o1 += si * q8(w1[i]);
        }
        o1 += rintf(fc1_b[s * 32 + lane]);
        float ac1 = clip127(o1 * (1.f / 64.f));
        float v2  = ac1 * q8(fc2_w[s * 32 + lane]);

        float pw = 0.f, pb = 0.f;
        {
            const int ws = woff[b], we = (b + 1 < B) ? woff[b + 1] : n_wf;
            const int bs = boff[b], be = (b + 1 < B) ? boff[b + 1] : n_bf;
            for (int k = ws + lane; k < we; k += 32)
                pw += rintf(psqt[(size_t)wfeat[k] * NBUCK + s]);
            for (int k = bs + lane; k < be; k += 32)
                pb += rintf(psqt[(size_t)bfeat[k] * NBUCK + s]);
        }
        #pragma unroll
        for (int o = 16; o; o >>= 1) {
            v2 += __shfl_down_sync(0xffffffffu, v2, o);
            pw += __shfl_down_sync(0xffffffffu, pw, o);
            pb += __shfl_down_sync(0xffffffffu, pb, o);
        }
        if (lane == 0) {
            float scalar = v2 + rintf(fc2_b[s]);
            float skip   = s_o0[15] * (9600.f / 8128.f);
            float psqt_v = (st ? (pb - pw) : (pw - pb)) * 0.5f;
            out[b] = (psqt_v + scalar + skip) * (1.f / 16.f);
        }
    }
}

extern "C" void kernel_launch(void* const* d_in, const int* in_sizes, int n_in,
                              void* d_out, int out_size) {
    const int*   wfeat  = (const int*)d_in[0];
    const int*   woff   = (const int*)d_in[1];
    const int*   bfeat  = (const int*)d_in[2];
    const int*   boff   = (const int*)d_in[3];
    const int*   stm    = (const int*)d_in[4];
    const int*   bucket = (const int*)d_in[5];
    const float* ftw    = (const float*)d_in[6];
    const float* ftb    = (const float*)d_in[7];
    const float* psq    = (const float*)d_in[8];
    const float* fc0w   = (const float*)d_in[9];
    const float* fc0b   = (const float*)d_in[10];
    const float* fc1w   = (const float*)d_in[11];
    const float* fc1b   = (const float*)d_in[12];
    const float* fc2w   = (const float*)d_in[13];
    const float* fc2b   = (const float*)d_in[14];
    float* out = (float*)d_out;

    const int B    = in_sizes[4];
    const int n_wf = in_sizes[0];
    const int n_bf = in_sizes[2];
    const int n16  = in_sizes[6] / 16;
    const int nfc4 = in_sizes[9] / 4;

    k_quant<<<(n16 + 255) / 256, 256>>>(ftw, fc0w, n16, nfc4);
    k_main<<<B, 256>>>(wfeat, woff, bfeat, boff, stm, bucket, ftb, psq,
                       fc0b, fc1w, fc1b, fc2w, fc2b, out, B, n_wf, n_bf);
}

// round 11
// speedup vs baseline: 1.0927x; 1.0927x over previous
#include <cuda_runtime.h>
#include <cstdint>

// GungnirHalfKA fused NNUE eval for GB300.
// Inputs (metadata order):
//  0 w_feats  int32 [B*32]      1 w_offsets int32 [B]
//  2 b_feats  int32 [B*32]      3 b_offsets int32 [B]
//  4 stm      int32 [B]         5 bucket    int32 [B]
//  6 ft_weight f32 [45056,1024] 7 ft_bias   f32 [1024]
//  8 psqt_weight f32 [45056,8]
//  9 fc0_w f32 [8,16,1024]     10 fc0_b f32 [8,16]
// 11 fc1_w f32 [8,32,32]       12 fc1_b f32 [8,32]
// 13 fc2_w f32 [8,1,32]        14 fc2_b f32 [8,1]
// Output: f32 [B]
//
// fake_quant(ft_weight,16) values fit int8 (verified in round 3). Table is
// stored BIASED uint8 (q+128); sparse sums are carry-free packed uint16x2
// adds. 128-thread CTAs: thread = half(2) x 16-column slice(64); one LDG.128
// (__ldcg, L2-only) per feature per thread, accumulators fully in registers.

#define FT_IN  45056
#define FT_OUT 1024
#define NBUCK  8

__device__ unsigned char g_ftw_q[(size_t)FT_IN * FT_OUT];   // biased uint8, 46 MB
__device__ signed char   g_fc0_q[NBUCK * 16 * FT_OUT];      // signed int8, 128 KB

__device__ __forceinline__ unsigned int qbias8(float v) {
    return (unsigned int)fminf(fmaxf(rintf(v) + 128.f, 0.f), 255.f);
}

// Prelude: quantize ft_weight (biased uint8, 16 floats/thread) + fc0_w (int8).
__global__ void __launch_bounds__(256) k_quant(
    const float* __restrict__ ftw, const float* __restrict__ fc0w,
    int n16, int nfc4)
{
    const int i = blockIdx.x * blockDim.x + threadIdx.x;
    if (i < n16) {
        const float4* src = reinterpret_cast<const float4*>(ftw) + i * 4;
        float4 v0 = src[0], v1 = src[1], v2 = src[2], v3 = src[3];
        uint4 q;
        q.x = qbias8(v0.x) | (qbias8(v0.y) << 8) | (qbias8(v0.z) << 16) | (qbias8(v0.w) << 24);
        q.y = qbias8(v1.x) | (qbias8(v1.y) << 8) | (qbias8(v1.z) << 16) | (qbias8(v1.w) << 24);
        q.z = qbias8(v2.x) | (qbias8(v2.y) << 8) | (qbias8(v2.z) << 16) | (qbias8(v2.w) << 24);
        q.w = qbias8(v3.x) | (qbias8(v3.y) << 8) | (qbias8(v3.z) << 16) | (qbias8(v3.w) << 24);
        reinterpret_cast<uint4*>(g_ftw_q)[i] = q;
    }
    if (i < nfc4) {
        float4 v = reinterpret_cast<const float4*>(fc0w)[i];
        char4 q;
        q.x = (signed char)fminf(fmaxf(rintf(v.x), -128.f), 127.f);
        q.y = (signed char)fminf(fmaxf(rintf(v.y), -128.f), 127.f);
        q.z = (signed char)fminf(fmaxf(rintf(v.z), -128.f), 127.f);
        q.w = (signed char)fminf(fmaxf(rintf(v.w), -128.f), 127.f);
        reinterpret_cast<char4*>(g_fc0_q)[i] = q;
    }
}

__device__ __forceinline__ float clip127(float x) {
    return fminf(fmaxf(x, 0.f), 127.f);
}
__device__ __forceinline__ float q8(float x) {
    return fminf(fmaxf(rintf(x), -128.f), 127.f);
}
__device__ __forceinline__ float qb16(float x) {
    return fminf(fmaxf(rintf(x), -32768.f), 32767.f);
}

__global__ void __launch_bounds__(128) k_main(
    const int* __restrict__ wfeat, const int* __restrict__ woff,
    const int* __restrict__ bfeat, const int* __restrict__ boff,
    const int* __restrict__ stm,   const int* __restrict__ bucket,
    const float* __restrict__ ft_bias, const float* __restrict__ psqt,
    const float* __restrict__ fc0_b,
    const float* __restrict__ fc1_w, const float* __restrict__ fc1_b,
    const float* __restrict__ fc2_w, const float* __restrict__ fc2_b,
    float* __restrict__ out, int B, int n_wf, int n_bf)
{
    __shared__ float s_acc[2][FT_OUT];   // 8 KB
    __shared__ float s_ft[FT_OUT];       // 4 KB
    __shared__ float s_o0[16];

    const int b    = blockIdx.x;
    const int tid  = threadIdx.x;
    const int half = tid >> 6;           // 0: white, 1: black
    const int l16  = tid & 63;           // owns cols [16*l16, 16*l16+16)

    // ---- Phase 1: sparse gather, LDG.128 L2-only, packed uint16x2 accum ----
    const int* feats = half ? bfeat : wfeat;
    const int* offs  = half ? boff  : woff;
    const int  nf    = half ? n_bf  : n_wf;
    const int  start = offs[b];
    const int  end   = (b + 1 < B) ? offs[b + 1] : nf;

    unsigned int u0 = 0, u1 = 0, u2 = 0, u3 = 0, u4 = 0, u5 = 0, u6 = 0, u7 = 0;
    {
        const unsigned char* base = g_ftw_q + (unsigned)l16 * 16u;
        #pragma unroll 8
        for (int k = start; k < end; ++k) {
            const unsigned int f = (unsigned int)feats[k];
            uint4 v = __ldcg(reinterpret_cast<const uint4*>(base + ((size_t)f << 10)));
            u0 += __byte_perm(v.x, 0u, 0x4140);
            u1 += __byte_perm(v.x, 0u, 0x4342);
            u2 += __byte_perm(v.y, 0u, 0x4140);
            u3 += __byte_perm(v.y, 0u, 0x4342);
            u4 += __byte_perm(v.z, 0u, 0x4140);
            u5 += __byte_perm(v.z, 0u, 0x4342);
            u6 += __byte_perm(v.w, 0u, 0x4140);
            u7 += __byte_perm(v.w, 0u, 0x4342);
        }
    }
    {
        const float bias = 128.f * (float)(end - start);
        const float4* fb = reinterpret_cast<const float4*>(ft_bias) + l16 * 4;
        float4 b0 = fb[0], b1 = fb[1], b2 = fb[2], b3 = fb[3];
        float* dst = s_acc[half] + l16 * 16;
        dst[ 0] = (float)(u0 & 0xFFFFu) - bias + qb16(b0.x);
        dst[ 1] = (float)(u0 >> 16)     - bias + qb16(b0.y);
        dst[ 2] = (float)(u1 & 0xFFFFu) - bias + qb16(b0.z);
        dst[ 3] = (float)(u1 >> 16)     - bias + qb16(b0.w);
        dst[ 4] = (float)(u2 & 0xFFFFu) - bias + qb16(b1.x);
        dst[ 5] = (float)(u2 >> 16)     - bias + qb16(b1.y);
        dst[ 6] = (float)(u3 & 0xFFFFu) - bias + qb16(b1.z);
        dst[ 7] = (float)(u3 >> 16)     - bias + qb16(b1.w);
        dst[ 8] = (float)(u4 & 0xFFFFu) - bias + qb16(b2.x);
        dst[ 9] = (float)(u4 >> 16)     - bias + qb16(b2.y);
        dst[10] = (float)(u5 & 0xFFFFu) - bias + qb16(b2.z);
        dst[11] = (float)(u5 >> 16)     - bias + qb16(b2.w);
        dst[12] = (float)(u6 & 0xFFFFu) - bias + qb16(b3.x);
        dst[13] = (float)(u6 >> 16)     - bias + qb16(b3.y);
        dst[14] = (float)(u7 & 0xFFFFu) - bias + qb16(b3.z);
        dst[15] = (float)(u7 >> 16)     - bias + qb16(b3.w);
    }
    __syncthreads();

    // ---- Phase 2: stm select + pairwise clipped product ----
    const int st = stm[b];
    const float* as = s_acc[st];
    const float* ao = s_acc[st ^ 1];
    #pragma unroll
    for (int j = tid; j < 512; j += 128) {
        float lo = clip127(as[j]);
        float hi = clip127(as[j + 512]);
        s_ft[j] = lo * hi * (1.f / 128.f);
        lo = clip127(ao[j]);
        hi = clip127(ao[j + 512]);
        s_ft[j + 512] = lo * hi * (1.f / 128.f);
    }
    __syncthreads();

    // ---- Phase 3: fc0 (16 x 1024), int8 weights, 4 warps x 4 outputs ----
    const int s    = bucket[b];
    const int warp = tid >> 5;
    const int lane = tid & 31;
    {
        const char4*  w8  = reinterpret_cast<const char4*>(g_fc0_q + s * 16 * FT_OUT);
        const float4* ft4 = reinterpret_cast<const float4*>(s_ft);
        const int o0 = warp * 4;
        float oa = 0.f, ob = 0.f, oc = 0.f, od = 0.f;
        #pragma unroll
        for (int k = 0; k < 8; ++k) {
            const int idx = lane + 32 * k;
            float4 f = ft4[idx];
            char4 wa = w8[(o0 + 0) * 256 + idx];
            char4 wb = w8[(o0 + 1) * 256 + idx];
            char4 wc = w8[(o0 + 2) * 256 + idx];
            char4 wd = w8[(o0 + 3) * 256 + idx];
            oa += f.x * wa.x + f.y * wa.y + f.z * wa.z + f.w * wa.w;
            ob += f.x * wb.x + f.y * wb.y + f.z * wb.z + f.w * wb.w;
            oc += f.x * wc.x + f.y * wc.y + f.z * wc.z + f.w * wc.w;
            od += f.x * wd.x + f.y * wd.y + f.z * wd.z + f.w * wd.w;
        }
        #pragma unroll
        for (int o = 16; o; o >>= 1) {
            oa += __shfl_down_sync(0xffffffffu, oa, o);
            ob += __shfl_down_sync(0xffffffffu, ob, o);
            oc += __shfl_down_sync(0xffffffffu, oc, o);
            od += __shfl_down_sync(0xffffffffu, od, o);
        }
        if (lane == 0) {
            s_o0[o0 + 0] = oa + rintf(fc0_b[s * 16 + o0 + 0]);
            s_o0[o0 + 1] = ob + rintf(fc0_b[s * 16 + o0 + 1]);
            s_o0[o0 + 2] = oc + rintf(fc0_b[s * 16 + o0 + 2]);
            s_o0[o0 + 3] = od + rintf(fc0_b[s * 16 + o0 + 3]);
        }
    }
    __syncthreads();

    // ---- Phase 4: slab -> fc1 -> fc2 -> skip + psqt (warp 0 only) ----
    if (warp == 0) {
        float slab = 0.f;
        if (lane < 15) {
            float v = s_o0[lane];
            slab = fminf(v * v * (1.f / 524288.f), 127.f);
        } else if (lane < 30) {
            slab = clip127(s_o0[lane - 15] * (1.f / 64.f));
        }

        const float* w1 = fc1_w + (s * 32 + lane) * 32;
        float o1 = 0.f;
        #pragma unroll
        for (int i = 0; i < 32; ++i) {
            float si = __shfl_sync(0xffffffffu, slab, i);
            o1 += si * q8(w1[i]);
        }
        o1 += rintf(fc1_b[s * 32 + lane]);
        float ac1 = clip127(o1 * (1.f / 64.f));
        float v2  = ac1 * q8(fc2_w[s * 32 + lane]);

        float pw = 0.f, pb = 0.f;
        {
            const int ws = woff[b], we = (b + 1 < B) ? woff[b + 1] : n_wf;
            const int bs = boff[b], be = (b + 1 < B) ? boff[b + 1] : n_bf;
            for (int k = ws + lane; k < we; k += 32)
                pw += rintf(psqt[(size_t)wfeat[k] * NBUCK + s]);
            for (int k = bs + lane; k < be; k += 32)
                pb += rintf(psqt[(size_t)bfeat[k] * NBUCK + s]);
        }
        #pragma unroll
        for (int o = 16; o; o >>= 1) {
            v2 += __shfl_down_sync(0xffffffffu, v2, o);
            pw += __shfl_down_sync(0xffffffffu, pw, o);
            pb += __shfl_down_sync(0xffffffffu, pb, o);
        }
        if (lane == 0) {
            float scalar = v2 + rintf(fc2_b[s]);
            float skip   = s_o0[15] * (9600.f / 8128.f);
            float psqt_v = (st ? (pb - pw) : (pw - pb)) * 0.5f;
            out[b] = (psqt_v + scalar + skip) * (1.f / 16.f);
        }
    }
}

extern "C" void kernel_launch(void* const* d_in, const int* in_sizes, int n_in,
                              void* d_out, int out_size) {
    const int*   wfeat  = (const int*)d_in[0];
    const int*   woff   = (const int*)d_in[1];
    const int*   bfeat  = (const int*)d_in[2];
    const int*   boff   = (const int*)d_in[3];
    const int*   stm    = (const int*)d_in[4];
    const int*   bucket = (const int*)d_in[5];
    const float* ftw    = (const float*)d_in[6];
    const float* ftb    = (const float*)d_in[7];
    const float* psq    = (const float*)d_in[8];
    const float* fc0w   = (const float*)d_in[9];
    const float* fc0b   = (const float*)d_in[10];
    const float* fc1w   = (const float*)d_in[11];
    const float* fc1b   = (const float*)d_in[12];
    const float* fc2w   = (const float*)d_in[13];
    const float* fc2b   = (const float*)d_in[14];
    float* out = (float*)d_out;

    const int B    = in_sizes[4];
    const int n_wf = in_sizes[0];
    const int n_bf = in_sizes[2];
    const int n16  = in_sizes[6] / 16;
    const int nfc4 = in_sizes[9] / 4;

    k_quant<<<(n16 + 255) / 256, 256>>>(ftw, fc0w, n16, nfc4);
    k_main<<<B, 128>>>(wfeat, woff, bfeat, boff, stm, bucket, ftb, psq,
                       fc0b, fc1w, fc1b, fc2w, fc2b, out, B, n_wf, n_bf);
}